// round 3
// baseline (speedup 1.0000x reference)
#include <cuda_runtime.h>
#include <cstdint>
#include <math.h>

// Problem constants
#define HID   4096
#define NHEAD 32
#define HDIM  128
#define BATCH 2
#define SEQ   1024
#define MTOK  2048          // BATCH*SEQ
#define BHTOT 64            // BATCH*NHEAD
#define QSCALE 0.08838834764831845f   // 1/sqrt(128)

// -------- scratch (no allocation allowed: __device__ globals) --------
__device__ float g_xn [MTOK * HID];            // layernormed input   [2048,4096]
__device__ float g_q  [BHTOT * SEQ * HDIM];    // [b,h,s,d]
__device__ float g_k  [BHTOT * SEQ * HDIM];
__device__ float g_v  [BHTOT * SEQ * HDIM];
__device__ float g_S  [67108864];              // scores/probs [64,1024,1024]
__device__ float g_ctx[MTOK * HID];            // [b,s,h,d] = [2048,4096]

// -------- helpers --------
__device__ __forceinline__ float f2tf(float x) {
    uint32_t u;
    asm("cvt.rna.tf32.f32 %0, %1;" : "=r"(u) : "f"(x));
    return __uint_as_float(u);
}

__device__ __forceinline__ void mma8(float c[4], const uint32_t a[4], const uint32_t b[2]) {
    asm volatile(
        "mma.sync.aligned.m16n8k8.row.col.f32.tf32.tf32.f32 "
        "{%0,%1,%2,%3}, {%4,%5,%6,%7}, {%8,%9}, {%0,%1,%2,%3};"
        : "+f"(c[0]), "+f"(c[1]), "+f"(c[2]), "+f"(c[3])
        : "r"(a[0]), "r"(a[1]), "r"(a[2]), "r"(a[3]), "r"(b[0]), "r"(b[1]));
}

template<bool IS_MAX>
__device__ __forceinline__ float block_reduce(float v) {
    __shared__ float sh[8];
    __syncthreads();   // protect reuse across calls
    #pragma unroll
    for (int o = 16; o; o >>= 1) {
        float t = __shfl_xor_sync(0xffffffffu, v, o);
        v = IS_MAX ? fmaxf(v, t) : (v + t);
    }
    if ((threadIdx.x & 31) == 0) sh[threadIdx.x >> 5] = v;
    __syncthreads();
    v = sh[0];
    #pragma unroll
    for (int i = 1; i < 8; i++) v = IS_MAX ? fmaxf(v, sh[i]) : (v + sh[i]);
    return v;
}

// -------- layernorm: one block per token row --------
__global__ void ln_kernel(const float* __restrict__ x, const float* __restrict__ w,
                          const float* __restrict__ bb, float* __restrict__ o) {
    size_t base = (size_t)blockIdx.x * HID;
    float4 vx[4];
    float s = 0.f, s2 = 0.f;
    #pragma unroll
    for (int i = 0; i < 4; i++) {
        vx[i] = *(const float4*)(x + base + (size_t)(threadIdx.x + i * 256) * 4);
        s  += vx[i].x + vx[i].y + vx[i].z + vx[i].w;
        s2 += vx[i].x * vx[i].x + vx[i].y * vx[i].y + vx[i].z * vx[i].z + vx[i].w * vx[i].w;
    }
    s  = block_reduce<false>(s);
    s2 = block_reduce<false>(s2);
    float mu  = s * (1.f / HID);
    float var = s2 * (1.f / HID) - mu * mu;
    float rs  = rsqrtf(var + 1e-5f);
    #pragma unroll
    for (int i = 0; i < 4; i++) {
        int c = (threadIdx.x + i * 256) * 4;
        float4 wv = *(const float4*)(w + c);
        float4 bv = *(const float4*)(bb + c);
        float4 r;
        r.x = (vx[i].x - mu) * rs * wv.x + bv.x;
        r.y = (vx[i].y - mu) * rs * wv.y + bv.y;
        r.z = (vx[i].z - mu) * rs * wv.z + bv.z;
        r.w = (vx[i].w - mu) * rs * wv.w + bv.w;
        *(float4*)(o + base + c) = r;
    }
}

// -------- row softmax over 1024 cols, in place --------
__global__ void softmax_kernel(float* __restrict__ S) {
    size_t base = (size_t)blockIdx.x * 1024;
    float4 v = *(float4*)(S + base + (size_t)threadIdx.x * 4);
    float m = fmaxf(fmaxf(v.x, v.y), fmaxf(v.z, v.w));
    m = block_reduce<true>(m);
    v.x = __expf(v.x - m); v.y = __expf(v.y - m);
    v.z = __expf(v.z - m); v.w = __expf(v.w - m);
    float s = v.x + v.y + v.z + v.w;
    s = block_reduce<false>(s);
    float inv = 1.0f / s;
    v.x *= inv; v.y *= inv; v.z *= inv; v.w *= inv;
    *(float4*)(S + base + (size_t)threadIdx.x * 4) = v;
}

// -------- generic TF32 GEMM, 128x128x32 tile, 256 threads, fused epilogues --------
// MODE 0: QKV  : C[m,n] += bias[n]; scatter to q/k/v [b,h,s,d], q scaled
// MODE 1: QK^T : C += causal + mask; write S  (A,B batched by blockIdx.z; BT=true)
// MODE 2: PV   : write ctx [b,s,h,d]; K-loop truncated at causal boundary
// MODE 3: proj : plain store to out [m*N+n]
constexpr int BM = 128, BN = 128, BK = 32, PAD = 4;

template<int MODE>
__device__ __forceinline__ void epi_store(int m, int n, float val, int zb, int N,
                                          const float* __restrict__ bias,
                                          const float* __restrict__ mask,
                                          float* __restrict__ out,
                                          float* __restrict__ oq,
                                          float* __restrict__ okk,
                                          float* __restrict__ ov) {
    if (MODE == 0) {
        val += bias[n];
        int which = n >> 12;            // 0=q 1=k 2=v
        int nn = n & 4095;
        int h = nn >> 7, d = nn & 127;
        int b = m >> 10, s = m & 1023;
        size_t off = ((size_t)((b * NHEAD + h) * 1024 + s)) * 128 + d;
        if (which == 0)      oq [off] = val * QSCALE;
        else if (which == 1) okk[off] = val;
        else                 ov [off] = val;
    } else if (MODE == 1) {
        int b = zb >> 5;
        val += mask[b * 1024 + n];
        if (n > m) val += -10000.0f;
        out[(size_t)zb * 1048576 + (size_t)m * 1024 + n] = val;
    } else if (MODE == 2) {
        int b = zb >> 5, h = zb & 31;
        out[(((size_t)(b * 1024 + m)) * NHEAD + h) * 128 + n] = val;
    } else {
        out[(size_t)m * N + n] = val;
    }
}

template<int MODE, bool BT>
__global__ void gemm_tf32(const float* __restrict__ A, const float* __restrict__ Bm,
                          float* __restrict__ out,
                          int M, int N, int K, long long sA, long long sB,
                          const float* __restrict__ bias, const float* __restrict__ mask,
                          float* __restrict__ oq, float* __restrict__ okk,
                          float* __restrict__ ov) {
    __shared__ float As[BM][BK + PAD];   // [m][k], stride 36 -> conflict-free frag loads
    __shared__ float Bs[BN][BK + PAD];   // [n][k]

    const int tid = threadIdx.x;
    const int m0 = blockIdx.y * BM, n0 = blockIdx.x * BN;
    const int zb = blockIdx.z;
    A  += (long long)zb * sA;
    Bm += (long long)zb * sB;

    const int wid = tid >> 5, lane = tid & 31;
    const int wm = wid & 1, wn = wid >> 1;     // 2 x 4 warp grid; warp tile 64x32
    const int g = lane >> 2, qt = lane & 3;

    float acc[4][4][4];
    #pragma unroll
    for (int a = 0; a < 4; a++)
        #pragma unroll
        for (int b = 0; b < 4; b++)
            #pragma unroll
            for (int c = 0; c < 4; c++) acc[a][b][c] = 0.f;

    const int ktot = (MODE == 2) ? (m0 + BM) / BK : K / BK;   // causal truncation for PV
    const bool skip = (MODE == 1) && (n0 > m0 + BM - 1);      // fully-masked score block

    float4 pa[4], pb[4];

    auto load_regs = [&](int kt) {
        const int k0 = kt * BK;
        #pragma unroll
        for (int i = 0; i < 4; i++) {
            int lin = tid + i * 256;
            int r = lin >> 3, c4 = lin & 7;
            pa[i] = *(const float4*)(A + (size_t)(m0 + r) * K + k0 + c4 * 4);
        }
        #pragma unroll
        for (int i = 0; i < 4; i++) {
            int lin = tid + i * 256;
            if (BT) {  // B is [N,K] row-major (C = A @ B^T)
                int r = lin >> 3, c4 = lin & 7;
                pb[i] = *(const float4*)(Bm + (size_t)(n0 + r) * K + k0 + c4 * 4);
            } else {   // B is [K,N] row-major
                int kr = lin >> 5, c4 = lin & 31;
                pb[i] = *(const float4*)(Bm + (size_t)(k0 + kr) * N + n0 + c4 * 4);
            }
        }
    };
    auto store_tile = [&]() {
        #pragma unroll
        for (int i = 0; i < 4; i++) {
            int lin = tid + i * 256;
            int r = lin >> 3, c4 = lin & 7;
            float4 t;
            t.x = f2tf(pa[i].x); t.y = f2tf(pa[i].y);
            t.z = f2tf(pa[i].z); t.w = f2tf(pa[i].w);
            *(float4*)&As[r][c4 * 4] = t;
        }
        #pragma unroll
        for (int i = 0; i < 4; i++) {
            int lin = tid + i * 256;
            if (BT) {
                int r = lin >> 3, c4 = lin & 7;
                float4 t;
                t.x = f2tf(pb[i].x); t.y = f2tf(pb[i].y);
                t.z = f2tf(pb[i].z); t.w = f2tf(pb[i].w);
                *(float4*)&Bs[r][c4 * 4] = t;
            } else {   // transpose into [n][k]
                int kr = lin >> 5, c4 = lin & 31;
                Bs[c4 * 4 + 0][kr] = f2tf(pb[i].x);
                Bs[c4 * 4 + 1][kr] = f2tf(pb[i].y);
                Bs[c4 * 4 + 2][kr] = f2tf(pb[i].z);
                Bs[c4 * 4 + 3][kr] = f2tf(pb[i].w);
            }
        }
    };

    if (!skip) {
        load_regs(0);
        store_tile();
        __syncthreads();
        for (int kt = 0; kt < ktot; kt++) {
            const bool more = (kt + 1 < ktot);
            if (more) load_regs(kt + 1);   // global prefetch overlaps compute
            #pragma unroll
            for (int ks = 0; ks < 4; ks++) {
                const int kb = ks * 8;
                uint32_t af[4][4], bf[4][2];
                #pragma unroll
                for (int im = 0; im < 4; im++) {
                    int rb = wm * 64 + im * 16;
                    af[im][0] = __float_as_uint(As[rb + g    ][kb + qt    ]);
                    af[im][1] = __float_as_uint(As[rb + g + 8][kb + qt    ]);
                    af[im][2] = __float_as_uint(As[rb + g    ][kb + qt + 4]);
                    af[im][3] = __float_as_uint(As[rb + g + 8][kb + qt + 4]);
                }
                #pragma unroll
                for (int jn = 0; jn < 4; jn++) {
                    int cb = wn * 32 + jn * 8;
                    bf[jn][0] = __float_as_uint(Bs[cb + g][kb + qt    ]);
                    bf[jn][1] = __float_as_uint(Bs[cb + g][kb + qt + 4]);
                }
                #pragma unroll
                for (int im = 0; im < 4; im++)
                    #pragma unroll
                    for (int jn = 0; jn < 4; jn++)
                        mma8(acc[im][jn], af[im], bf[jn]);
            }
            __syncthreads();
            if (more) { store_tile(); __syncthreads(); }
        }
    }

    // epilogue
    #pragma unroll
    for (int im = 0; im < 4; im++) {
        #pragma unroll
        for (int jn = 0; jn < 4; jn++) {
            int mr = m0 + wm * 64 + im * 16 + g;
            int nc = n0 + wn * 32 + jn * 8 + 2 * qt;
            epi_store<MODE>(mr,     nc,     acc[im][jn][0], zb, N, bias, mask, out, oq, okk, ov);
            epi_store<MODE>(mr,     nc + 1, acc[im][jn][1], zb, N, bias, mask, out, oq, okk, ov);
            epi_store<MODE>(mr + 8, nc,     acc[im][jn][2], zb, N, bias, mask, out, oq, okk, ov);
            epi_store<MODE>(mr + 8, nc + 1, acc[im][jn][3], zb, N, bias, mask, out, oq, okk, ov);
        }
    }
}

// -------- launch --------
extern "C" void kernel_launch(void* const* d_in, const int* in_sizes, int n_in,
                              void* d_out, int out_size) {
    const float* x     = (const float*)d_in[0];
    const float* mask  = (const float*)d_in[1];
    const float* nw    = (const float*)d_in[2];
    const float* nb    = (const float*)d_in[3];
    const float* qkvw  = (const float*)d_in[4];
    const float* qkvb  = (const float*)d_in[5];
    const float* ow    = (const float*)d_in[6];
    float* out = (float*)d_out;

    float *xn, *q, *k, *v, *S, *ctx;
    cudaGetSymbolAddress((void**)&xn,  g_xn);
    cudaGetSymbolAddress((void**)&q,   g_q);
    cudaGetSymbolAddress((void**)&k,   g_k);
    cudaGetSymbolAddress((void**)&v,   g_v);
    cudaGetSymbolAddress((void**)&S,   g_S);
    cudaGetSymbolAddress((void**)&ctx, g_ctx);

    // 1) layernorm
    ln_kernel<<<MTOK, 256>>>(x, nw, nb, xn);

    // 2) QKV GEMM + bias + head scatter (q pre-scaled)
    gemm_tf32<0, false><<<dim3(96, 16, 1), 256>>>(
        xn, qkvw, nullptr, MTOK, 3 * HID, HID, 0, 0, qkvb, nullptr, q, k, v);

    // 3) scores = q @ k^T (+causal +mask), batched over 64 (b,h)
    gemm_tf32<1, true><<<dim3(8, 8, BHTOT), 256>>>(
        q, k, S, SEQ, SEQ, HDIM, 131072LL, 131072LL, nullptr, mask,
        nullptr, nullptr, nullptr);

    // 4) softmax rows (in place)
    softmax_kernel<<<BHTOT * SEQ, 256>>>(S);

    // 5) ctx = P @ V, batched, causal-truncated K loop
    gemm_tf32<2, false><<<dim3(1, 8, BHTOT), 256>>>(
        S, v, ctx, SEQ, HDIM, SEQ, 1048576LL, 131072LL, nullptr, nullptr,
        nullptr, nullptr, nullptr);

    // 6) out = ctx @ attn_ow
    gemm_tf32<3, false><<<dim3(32, 16, 1), 256>>>(
        ctx, ow, out, MTOK, HID, HID, 0, 0, nullptr, nullptr,
        nullptr, nullptr, nullptr);
}

// round 5
// speedup vs baseline: 1.9139x; 1.9139x over previous
#include <cuda_runtime.h>
#include <cstdint>
#include <math.h>

// Problem constants
#define HID   4096
#define NHEAD 32
#define HDIM  128
#define BATCH 2
#define SEQ   1024
#define MTOK  2048
#define BHTOT 64
#define QSCALE 0.08838834764831845f   // 1/sqrt(128)

// -------- scratch (__device__ globals; no allocation allowed) --------
__device__ float g_xn [MTOK * HID];            // rna-rounded layernorm output
__device__ float g_q  [BHTOT * SEQ * HDIM];    // [bh][s][d], rounded, pre-scaled
__device__ float g_k  [BHTOT * SEQ * HDIM];    // [bh][s][d], rounded
__device__ float g_v  [BHTOT * SEQ * HDIM];    // [bh][d][s], rounded, TRANSPOSED
__device__ float g_w  [67108864];              // qkv_w^T (50331648) + ow^T (16777216)
__device__ float g_ctx[MTOK * HID];            // [b*s][h*d], rounded

// -------- low-level helpers --------
__device__ __forceinline__ float f2tf(float x) {
    uint32_t u;
    asm("cvt.rna.tf32.f32 %0, %1;" : "=r"(u) : "f"(x));
    return __uint_as_float(u);
}
__device__ __forceinline__ uint32_t sa(const void* p) {
    return (uint32_t)__cvta_generic_to_shared(p);
}
__device__ __forceinline__ void cp16(uint32_t s, const void* g) {
    asm volatile("cp.async.cg.shared.global [%0], [%1], 16;\n" :: "r"(s), "l"(g));
}
__device__ __forceinline__ void cp_commit() {
    asm volatile("cp.async.commit_group;\n");
}
template<int N>
__device__ __forceinline__ void cp_wait() {
    asm volatile("cp.async.wait_group %0;\n" :: "n"(N));
}
// ldmatrix x4 on 32-bit data: each 16B "row" = 4 tf32; per 8x8(b16) matrix,
// lane i receives the tf32 at (row i>>2, col i&3) -> exactly the tf32 mma frag.
__device__ __forceinline__ void ldsm4(uint32_t r[4], uint32_t a) {
    asm volatile("ldmatrix.sync.aligned.m8n8.x4.shared.b16 {%0,%1,%2,%3}, [%4];"
        : "=r"(r[0]), "=r"(r[1]), "=r"(r[2]), "=r"(r[3]) : "r"(a));
}
__device__ __forceinline__ void mma8(float c[4], const uint32_t a[4],
                                     uint32_t b0, uint32_t b1) {
    asm volatile(
        "mma.sync.aligned.m16n8k8.row.col.f32.tf32.tf32.f32 "
        "{%0,%1,%2,%3}, {%4,%5,%6,%7}, {%8,%9}, {%0,%1,%2,%3};"
        : "+f"(c[0]), "+f"(c[1]), "+f"(c[2]), "+f"(c[3])
        : "r"(a[0]), "r"(a[1]), "r"(a[2]), "r"(a[3]), "r"(b0), "r"(b1));
}

__device__ __forceinline__ float block_sum(float v) {
    __shared__ float sh[8];
    __syncthreads();
    #pragma unroll
    for (int o = 16; o; o >>= 1) v += __shfl_xor_sync(0xffffffffu, v, o);
    if ((threadIdx.x & 31) == 0) sh[threadIdx.x >> 5] = v;
    __syncthreads();
    v = sh[0];
    #pragma unroll
    for (int i = 1; i < 8; i++) v += sh[i];
    return v;
}

// -------- weight prep: transpose [R][C] -> [C][R] with rna rounding --------
__global__ void transpose_round(const float* __restrict__ in, float* __restrict__ out,
                                int R, int C) {
    __shared__ float t[32][33];
    const int tx = threadIdx.x & 31, ty = threadIdx.x >> 5;
    const int c0 = blockIdx.x * 32, r0 = blockIdx.y * 32;
    #pragma unroll
    for (int i = 0; i < 4; i++)
        t[ty + i * 8][tx] = in[(size_t)(r0 + ty + i * 8) * C + c0 + tx];
    __syncthreads();
    #pragma unroll
    for (int i = 0; i < 4; i++)
        out[(size_t)(c0 + ty + i * 8) * R + r0 + tx] = f2tf(t[tx][ty + i * 8]);
}

// -------- layernorm (rna-rounded output) --------
__global__ void ln_kernel(const float* __restrict__ x, const float* __restrict__ w,
                          const float* __restrict__ bb, float* __restrict__ o) {
    size_t base = (size_t)blockIdx.x * HID;
    float4 vx[4];
    float s = 0.f, s2 = 0.f;
    #pragma unroll
    for (int i = 0; i < 4; i++) {
        vx[i] = *(const float4*)(x + base + (size_t)(threadIdx.x + i * 256) * 4);
        s  += vx[i].x + vx[i].y + vx[i].z + vx[i].w;
        s2 += vx[i].x * vx[i].x + vx[i].y * vx[i].y + vx[i].z * vx[i].z + vx[i].w * vx[i].w;
    }
    s  = block_sum(s);
    s2 = block_sum(s2);
    float mu  = s * (1.f / HID);
    float var = s2 * (1.f / HID) - mu * mu;
    float rs  = rsqrtf(var + 1e-5f);
    #pragma unroll
    for (int i = 0; i < 4; i++) {
        int c = (threadIdx.x + i * 256) * 4;
        float4 wv = *(const float4*)(w + c);
        float4 bv = *(const float4*)(bb + c);
        float4 r;
        r.x = f2tf((vx[i].x - mu) * rs * wv.x + bv.x);
        r.y = f2tf((vx[i].y - mu) * rs * wv.y + bv.y);
        r.z = f2tf((vx[i].z - mu) * rs * wv.z + bv.z);
        r.w = f2tf((vx[i].w - mu) * rs * wv.w + bv.w);
        *(float4*)(o + base + c) = r;
    }
}

// -------- GEMM: C[M,N] = A[M,K] @ B[N,K]^T, 128x128x32, cp.async 3-stage + ldmatrix --------
// MODE 0: QKV epilogue (+bias, scatter q/k/v; q scaled; v transposed; all rounded)
// MODE 3: plain store
template<int MODE>
__device__ __forceinline__ void epi(int m, int n, float val, int N,
                                    const float* __restrict__ bias,
                                    float* __restrict__ out, float* __restrict__ oq,
                                    float* __restrict__ ok_, float* __restrict__ ov) {
    if (MODE == 0) {
        val += bias[n];
        int which = n >> 12, nn = n & 4095;
        int h = nn >> 7, d = nn & 127, b = m >> 10, s = m & 1023;
        int bh = b * NHEAD + h;
        if (which == 0)      oq [((size_t)bh * 1024 + s) * 128 + d] = f2tf(val * QSCALE);
        else if (which == 1) ok_[((size_t)bh * 1024 + s) * 128 + d] = f2tf(val);
        else                 ov [((size_t)bh * 128 + d) * 1024 + s] = f2tf(val);
    } else {
        out[(size_t)m * N + n] = val;
    }
}

template<int MODE>
__global__ void __launch_bounds__(256, 1) gemm_k(
    const float* __restrict__ A, const float* __restrict__ B, float* __restrict__ out,
    int N, int K, const float* __restrict__ bias,
    float* __restrict__ oq, float* __restrict__ ok_, float* __restrict__ ov) {
    extern __shared__ float sm[];
    const int tid = threadIdx.x, lane = tid & 31, w = tid >> 5;
    const int wm = w & 1, wn = w >> 1, g = lane >> 2, qt = lane & 3;
    const int m0 = blockIdx.y * 128, n0 = blockIdx.x * 128;
    const int KT = K / 32;
    const uint32_t smb = sa(sm);

    float acc[4][4][4];
    #pragma unroll
    for (int a = 0; a < 4; a++)
        #pragma unroll
        for (int b = 0; b < 4; b++)
            #pragma unroll
            for (int c = 0; c < 4; c++) acc[a][b][c] = 0.f;

    auto issue = [&](int kt) {
        const int st = kt % 3;
        const uint32_t sA = smb + (uint32_t)st * 9216u * 4u;
        const uint32_t sB = sA + 4608u * 4u;
        const int k0 = kt * 32;
        #pragma unroll
        for (int i = 0; i < 4; i++) {
            int id = tid + i * 256;
            int r = id >> 3, c = (id & 7) * 4;
            cp16(sA + (uint32_t)(r * 36 + c) * 4u, A + (size_t)(m0 + r) * K + k0 + c);
        }
        #pragma unroll
        for (int i = 0; i < 4; i++) {
            int id = tid + i * 256;
            int r = id >> 3, c = (id & 7) * 4;
            cp16(sB + (uint32_t)(r * 36 + c) * 4u, B + (size_t)(n0 + r) * K + k0 + c);
        }
    };

    issue(0); cp_commit();
    issue(1); cp_commit();

    const int arow = wm * 64 + (lane & 7) + (lane & 8);
    const int acol = 4 * (lane >> 4);
    const int brow = (lane & 7) + 8 * (lane >> 4);
    const int bcol = 4 * ((lane >> 3) & 1);

    for (int kt = 0; kt < KT; kt++) {
        cp_wait<1>();
        __syncthreads();
        if (kt + 2 < KT) issue(kt + 2);
        cp_commit();
        const int st = kt % 3;
        const uint32_t sA = smb + (uint32_t)st * 9216u * 4u;
        const uint32_t sB = sA + 4608u * 4u;
        #pragma unroll
        for (int ks = 0; ks < 4; ks++) {
            const int kb = ks * 8;
            uint32_t af[4][4], bf[2][4];
            #pragma unroll
            for (int im = 0; im < 4; im++)
                ldsm4(af[im], sA + (uint32_t)((arow + im * 16) * 36 + kb + acol) * 4u);
            #pragma unroll
            for (int p = 0; p < 2; p++)
                ldsm4(bf[p], sB + (uint32_t)((wn * 32 + p * 16 + brow) * 36 + kb + bcol) * 4u);
            #pragma unroll
            for (int im = 0; im < 4; im++)
                #pragma unroll
                for (int jn = 0; jn < 4; jn++)
                    mma8(acc[im][jn], af[im], bf[jn >> 1][(jn & 1) * 2],
                         bf[jn >> 1][(jn & 1) * 2 + 1]);
        }
    }

    #pragma unroll
    for (int im = 0; im < 4; im++) {
        int mr = m0 + wm * 64 + im * 16 + g;
        #pragma unroll
        for (int jn = 0; jn < 4; jn++) {
            int nc = n0 + wn * 32 + jn * 8 + 2 * qt;
            epi<MODE>(mr,     nc,     acc[im][jn][0], N, bias, out, oq, ok_, ov);
            epi<MODE>(mr,     nc + 1, acc[im][jn][1], N, bias, out, oq, ok_, ov);
            epi<MODE>(mr + 8, nc,     acc[im][jn][2], N, bias, out, oq, ok_, ov);
            epi<MODE>(mr + 8, nc + 1, acc[im][jn][3], N, bias, out, oq, ok_, ov);
        }
    }
}

// -------- flash attention: per CTA one (bh, 128-row q block); 8 warps x 16 rows --------
// q [bh][s][d] (scaled+rounded), k [bh][s][d] (rounded), v [bh][d][s] (rounded)
// smem: Ks[128][132], Vs[128][132], Ps[128][132]
__global__ void __launch_bounds__(256, 1) flash_k(
    const float* __restrict__ q, const float* __restrict__ k, const float* __restrict__ v,
    const float* __restrict__ mask, float* __restrict__ ctx) {
    extern __shared__ float sm[];
    const int tid = threadIdx.x, lane = tid & 31, w = tid >> 5;
    const int g = lane >> 2, qt = lane & 3;
    const int qb = blockIdx.x, bh = blockIdx.y, b = bh >> 5, h = bh & 31;
    const size_t hoff = (size_t)bh * 131072;
    const uint32_t smb = sa(sm);
    const uint32_t sK = smb, sV = smb + 16896u * 4u, sP = smb + 33792u * 4u;

    const int arow = w * 16 + (lane & 7) + (lane & 8);
    const int acol = 4 * (lane >> 4);
    const int brow = (lane & 7) + 8 * (lane >> 4);
    const int bcol = 4 * ((lane >> 3) & 1);

    // stage Q through Ks buffer, pull fragments into registers (live whole kernel)
    #pragma unroll
    for (int i = 0; i < 16; i++) {
        int id = tid + i * 256;
        int r = id >> 5, c = (id & 31) * 4;
        cp16(sK + (uint32_t)(r * 132 + c) * 4u, q + hoff + (size_t)(qb * 128 + r) * 128 + c);
    }
    cp_commit(); cp_wait<0>();
    __syncthreads();
    uint32_t qf[16][4];
    #pragma unroll
    for (int kf = 0; kf < 16; kf++)
        ldsm4(qf[kf], sK + (uint32_t)(arow * 132 + kf * 8 + acol) * 4u);
    __syncthreads();

    float ctxa[16][4];
    #pragma unroll
    for (int i = 0; i < 16; i++) { ctxa[i][0] = ctxa[i][1] = ctxa[i][2] = ctxa[i][3] = 0.f; }
    float m1 = -1e30f, m2 = -1e30f, l1 = 0.f, l2 = 0.f;
    const int rl1 = w * 16 + g, rl2 = rl1 + 8;

    for (int j = 0; j <= qb; j++) {
        #pragma unroll
        for (int i = 0; i < 16; i++) {
            int id = tid + i * 256;
            int r = id >> 5, c = (id & 31) * 4;
            cp16(sK + (uint32_t)(r * 132 + c) * 4u, k + hoff + (size_t)(j * 128 + r) * 128 + c);
        }
        cp_commit();
        #pragma unroll
        for (int i = 0; i < 16; i++) {
            int id = tid + i * 256;
            int r = id >> 5, c = (id & 31) * 4;
            cp16(sV + (uint32_t)(r * 132 + c) * 4u, v + hoff + (size_t)r * 1024 + j * 128 + c);
        }
        cp_commit();
        cp_wait<1>();          // Ks ready; Vs still in flight (overlaps QK^T)
        __syncthreads();

        // S = Q @ K^T  (warp: 16 rows x 128 cols)
        float sacc[16][4];
        #pragma unroll
        for (int i = 0; i < 16; i++) { sacc[i][0] = sacc[i][1] = sacc[i][2] = sacc[i][3] = 0.f; }
        #pragma unroll
        for (int ks = 0; ks < 16; ks++) {
            #pragma unroll
            for (int p = 0; p < 8; p++) {
                uint32_t bf[4];
                ldsm4(bf, sK + (uint32_t)((p * 16 + brow) * 132 + ks * 8 + bcol) * 4u);
                mma8(sacc[2 * p],     qf[ks], bf[0], bf[1]);
                mma8(sacc[2 * p + 1], qf[ks], bf[2], bf[3]);
            }
        }

        // online softmax (row stats warp-local; lanes 4g..4g+3 share rows)
        const bool diag = (j == qb);
        float mx1 = -1e30f, mx2 = -1e30f;
        #pragma unroll
        for (int nf = 0; nf < 16; nf++) {
            int c0 = nf * 8 + 2 * qt, cg = j * 128 + c0;
            float mk0 = __ldg(mask + b * 1024 + cg);
            float mk1 = __ldg(mask + b * 1024 + cg + 1);
            float s0 = sacc[nf][0] + mk0, s1 = sacc[nf][1] + mk1;
            float s2 = sacc[nf][2] + mk0, s3 = sacc[nf][3] + mk1;
            if (diag) {
                if (c0     > rl1) s0 = -1e30f;
                if (c0 + 1 > rl1) s1 = -1e30f;
                if (c0     > rl2) s2 = -1e30f;
                if (c0 + 1 > rl2) s3 = -1e30f;
            }
            sacc[nf][0] = s0; sacc[nf][1] = s1; sacc[nf][2] = s2; sacc[nf][3] = s3;
            mx1 = fmaxf(mx1, fmaxf(s0, s1));
            mx2 = fmaxf(mx2, fmaxf(s2, s3));
        }
        #pragma unroll
        for (int o = 1; o < 4; o <<= 1) {
            mx1 = fmaxf(mx1, __shfl_xor_sync(0xffffffffu, mx1, o));
            mx2 = fmaxf(mx2, __shfl_xor_sync(0xffffffffu, mx2, o));
        }
        float mn1 = fmaxf(m1, mx1), mn2 = fmaxf(m2, mx2);
        float sc1 = __expf(m1 - mn1), sc2 = __expf(m2 - mn2);
        float su1 = 0.f, su2 = 0.f;
        #pragma unroll
        for (int nf = 0; nf < 16; nf++) {
            float p0 = __expf(sacc[nf][0] - mn1), p1 = __expf(sacc[nf][1] - mn1);
            float p2 = __expf(sacc[nf][2] - mn2), p3 = __expf(sacc[nf][3] - mn2);
            su1 += p0 + p1;
            su2 += p2 + p3;
            int c0 = nf * 8 + 2 * qt;
            *(float2*)(sm + 33792 + rl1 * 132 + c0) = make_float2(f2tf(p0), f2tf(p1));
            *(float2*)(sm + 33792 + rl2 * 132 + c0) = make_float2(f2tf(p2), f2tf(p3));
        }
        #pragma unroll
        for (int o = 1; o < 4; o <<= 1) {
            su1 += __shfl_xor_sync(0xffffffffu, su1, o);
            su2 += __shfl_xor_sync(0xffffffffu, su2, o);
        }
        l1 = l1 * sc1 + su1;
        l2 = l2 * sc2 + su2;
        m1 = mn1; m2 = mn2;
        #pragma unroll
        for (int nf = 0; nf < 16; nf++) {
            ctxa[nf][0] *= sc1; ctxa[nf][1] *= sc1;
            ctxa[nf][2] *= sc2; ctxa[nf][3] *= sc2;
        }
        cp_wait<0>();          // Vs ready
        __syncthreads();       // Ps visible to all

        // ctx += P @ V  (k-dim = s; B = Vs[d][s])
        #pragma unroll
        for (int ks = 0; ks < 16; ks++) {
            uint32_t paf[4];
            ldsm4(paf, sP + (uint32_t)(arow * 132 + ks * 8 + acol) * 4u);
            #pragma unroll
            for (int p = 0; p < 8; p++) {
                uint32_t bf[4];
                ldsm4(bf, sV + (uint32_t)((p * 16 + brow) * 132 + ks * 8 + bcol) * 4u);
                mma8(ctxa[2 * p],     paf, bf[0], bf[1]);
                mma8(ctxa[2 * p + 1], paf, bf[2], bf[3]);
            }
        }
        __syncthreads();       // done with Ks/Vs/Ps before next j overwrites
    }

    // epilogue: normalize, round, write [b*s][h*d]
    float il1 = 1.f / l1, il2 = 1.f / l2;
    const int sr1 = qb * 128 + rl1, sr2 = qb * 128 + rl2;
    #pragma unroll
    for (int nf = 0; nf < 16; nf++) {
        int d0 = nf * 8 + 2 * qt;
        size_t o1 = ((size_t)(b * 1024 + sr1)) * 4096 + h * 128 + d0;
        size_t o2 = ((size_t)(b * 1024 + sr2)) * 4096 + h * 128 + d0;
        *(float2*)(ctx + o1) = make_float2(f2tf(ctxa[nf][0] * il1), f2tf(ctxa[nf][1] * il1));
        *(float2*)(ctx + o2) = make_float2(f2tf(ctxa[nf][2] * il2), f2tf(ctxa[nf][3] * il2));
    }
}

// -------- launch --------
extern "C" void kernel_launch(void* const* d_in, const int* in_sizes, int n_in,
                              void* d_out, int out_size) {
    const float* x    = (const float*)d_in[0];
    const float* mask = (const float*)d_in[1];
    const float* nw   = (const float*)d_in[2];
    const float* nb   = (const float*)d_in[3];
    const float* qkvw = (const float*)d_in[4];
    const float* qkvb = (const float*)d_in[5];
    const float* ow   = (const float*)d_in[6];
    float* out = (float*)d_out;

    float *xn, *qv, *kv, *vv, *wbuf, *ctx;
    cudaGetSymbolAddress((void**)&xn,   g_xn);
    cudaGetSymbolAddress((void**)&qv,   g_q);
    cudaGetSymbolAddress((void**)&kv,   g_k);
    cudaGetSymbolAddress((void**)&vv,   g_v);
    cudaGetSymbolAddress((void**)&wbuf, g_w);
    cudaGetSymbolAddress((void**)&ctx,  g_ctx);
    float* wT  = wbuf;               // [12288][4096]
    float* owT = wbuf + 50331648;    // [4096][4096]

    cudaFuncSetAttribute(gemm_k<0>, cudaFuncAttributeMaxDynamicSharedMemorySize, 110592);
    cudaFuncSetAttribute(gemm_k<3>, cudaFuncAttributeMaxDynamicSharedMemorySize, 110592);
    cudaFuncSetAttribute(flash_k,   cudaFuncAttributeMaxDynamicSharedMemorySize, 202752);

    // weight prep: rna-round + transpose to [N][K]
    transpose_round<<<dim3(384, 128), 256>>>(qkvw, wT, 4096, 12288);
    transpose_round<<<dim3(128, 128), 256>>>(ow, owT, 4096, 4096);

    // layernorm (rounded output)
    ln_kernel<<<MTOK, 256>>>(x, nw, nb, xn);

    // QKV GEMM + bias + scatter (q scaled, v transposed, all rounded)
    gemm_k<0><<<dim3(96, 16), 256, 110592>>>(xn, wT, nullptr, 12288, HID, qkvb, qv, kv, vv);

    // fused flash attention -> ctx
    flash_k<<<dim3(8, BHTOT), 256, 202752>>>(qv, kv, vv, mask, ctx);

    // output projection
    gemm_k<3><<<dim3(32, 16), 256, 110592>>>(ctx, owT, out, HID, HID, nullptr,
                                             nullptr, nullptr, nullptr);
}

// round 7
// speedup vs baseline: 2.2864x; 1.1946x over previous
#include <cuda_runtime.h>
#include <cstdint>
#include <math.h>

// Problem constants
#define HID   4096
#define NHEAD 32
#define HDIM  128
#define BATCH 2
#define SEQ   1024
#define MTOK  2048
#define BHTOT 64
#define QSCALE 0.08838834764831845f   // 1/sqrt(128)

// -------- scratch (__device__ globals; no allocation allowed) --------
__device__ float g_xn [MTOK * HID];            // rna-rounded layernorm output
__device__ float g_q  [BHTOT * SEQ * HDIM];    // [bh][s][d], rounded, pre-scaled
__device__ float g_k  [BHTOT * SEQ * HDIM];    // [bh][s][d], rounded
__device__ float g_v  [BHTOT * SEQ * HDIM];    // [bh][d][s], rounded, TRANSPOSED
__device__ float g_w  [67108864];              // qkv_w^T (50331648) + ow^T (16777216)
__device__ float g_ctx[MTOK * HID];            // [b*s][h*d], rounded

// -------- low-level helpers --------
__device__ __forceinline__ float f2tf(float x) {
    uint32_t u;
    asm("cvt.rna.tf32.f32 %0, %1;" : "=r"(u) : "f"(x));
    return __uint_as_float(u);
}
__device__ __forceinline__ uint32_t sa(const void* p) {
    return (uint32_t)__cvta_generic_to_shared(p);
}
__device__ __forceinline__ void cp16(uint32_t s, const void* g) {
    asm volatile("cp.async.cg.shared.global [%0], [%1], 16;\n" :: "r"(s), "l"(g));
}
__device__ __forceinline__ void cp_commit() {
    asm volatile("cp.async.commit_group;\n");
}
template<int N>
__device__ __forceinline__ void cp_wait() {
    asm volatile("cp.async.wait_group %0;\n" :: "n"(N));
}
// ldmatrix x4 on 32-bit data: each 16B "row" = 4 tf32; lane i receives the
// tf32 at (row i>>2, col i&3) per 8x8 matrix -> exactly the tf32 mma frag.
__device__ __forceinline__ void ldsm4(uint32_t r[4], uint32_t a) {
    asm volatile("ldmatrix.sync.aligned.m8n8.x4.shared.b16 {%0,%1,%2,%3}, [%4];"
        : "=r"(r[0]), "=r"(r[1]), "=r"(r[2]), "=r"(r[3]) : "r"(a));
}
__device__ __forceinline__ void mma8(float c[4], const uint32_t a[4],
                                     uint32_t b0, uint32_t b1) {
    asm volatile(
        "mma.sync.aligned.m16n8k8.row.col.f32.tf32.tf32.f32 "
        "{%0,%1,%2,%3}, {%4,%5,%6,%7}, {%8,%9}, {%0,%1,%2,%3};"
        : "+f"(c[0]), "+f"(c[1]), "+f"(c[2]), "+f"(c[3])
        : "r"(a[0]), "r"(a[1]), "r"(a[2]), "r"(a[3]), "r"(b0), "r"(b1));
}

__device__ __forceinline__ float block_sum(float v) {
    __shared__ float sh[8];
    __syncthreads();
    #pragma unroll
    for (int o = 16; o; o >>= 1) v += __shfl_xor_sync(0xffffffffu, v, o);
    if ((threadIdx.x & 31) == 0) sh[threadIdx.x >> 5] = v;
    __syncthreads();
    v = sh[0];
    #pragma unroll
    for (int i = 1; i < 8; i++) v += sh[i];
    return v;
}

// -------- weight prep: transpose [R][C] -> [C][R] with rna rounding --------
__global__ void transpose_round(const float* __restrict__ in, float* __restrict__ out,
                                int R, int C) {
    __shared__ float t[32][33];
    const int tx = threadIdx.x & 31, ty = threadIdx.x >> 5;
    const int c0 = blockIdx.x * 32, r0 = blockIdx.y * 32;
    #pragma unroll
    for (int i = 0; i < 4; i++)
        t[ty + i * 8][tx] = in[(size_t)(r0 + ty + i * 8) * C + c0 + tx];
    __syncthreads();
    #pragma unroll
    for (int i = 0; i < 4; i++)
        out[(size_t)(c0 + ty + i * 8) * R + r0 + tx] = f2tf(t[tx][ty + i * 8]);
}

// -------- layernorm (rna-rounded output) --------
__global__ void ln_kernel(const float* __restrict__ x, const float* __restrict__ w,
                          const float* __restrict__ bb, float* __restrict__ o) {
    size_t base = (size_t)blockIdx.x * HID;
    float4 vx[4];
    float s = 0.f, s2 = 0.f;
    #pragma unroll
    for (int i = 0; i < 4; i++) {
        vx[i] = *(const float4*)(x + base + (size_t)(threadIdx.x + i * 256) * 4);
        s  += vx[i].x + vx[i].y + vx[i].z + vx[i].w;
        s2 += vx[i].x * vx[i].x + vx[i].y * vx[i].y + vx[i].z * vx[i].z + vx[i].w * vx[i].w;
    }
    s  = block_sum(s);
    s2 = block_sum(s2);
    float mu  = s * (1.f / HID);
    float var = s2 * (1.f / HID) - mu * mu;
    float rs  = rsqrtf(var + 1e-5f);
    #pragma unroll
    for (int i = 0; i < 4; i++) {
        int c = (threadIdx.x + i * 256) * 4;
        float4 wv = *(const float4*)(w + c);
        float4 bv = *(const float4*)(bb + c);
        float4 r;
        r.x = f2tf((vx[i].x - mu) * rs * wv.x + bv.x);
        r.y = f2tf((vx[i].y - mu) * rs * wv.y + bv.y);
        r.z = f2tf((vx[i].z - mu) * rs * wv.z + bv.z);
        r.w = f2tf((vx[i].w - mu) * rs * wv.w + bv.w);
        *(float4*)(o + base + c) = r;
    }
}

// -------- GEMM: C[M,N] = A[M,K] @ B[N,K]^T, 128x128x32, cp.async 2-stage + ldmatrix --------
// occupancy 2 CTAs/SM: 73.7KB smem, <=128 regs via launch_bounds(256,2)
// MODE 0: QKV epilogue (+bias, scatter q/k/v; q scaled; v transposed; all rounded)
// MODE 3: plain store
template<int MODE>
__device__ __forceinline__ void epi(int m, int n, float val, int N,
                                    const float* __restrict__ bias,
                                    float* __restrict__ out, float* __restrict__ oq,
                                    float* __restrict__ ok_, float* __restrict__ ov) {
    if (MODE == 0) {
        val += bias[n];
        int which = n >> 12, nn = n & 4095;
        int h = nn >> 7, d = nn & 127, b = m >> 10, s = m & 1023;
        int bh = b * NHEAD + h;
        if (which == 0)      oq [((size_t)bh * 1024 + s) * 128 + d] = f2tf(val * QSCALE);
        else if (which == 1) ok_[((size_t)bh * 1024 + s) * 128 + d] = f2tf(val);
        else                 ov [((size_t)bh * 128 + d) * 1024 + s] = f2tf(val);
    } else {
        out[(size_t)m * N + n] = val;
    }
}

template<int MODE>
__global__ void __launch_bounds__(256, 2) gemm_k(
    const float* __restrict__ A, const float* __restrict__ B, float* __restrict__ out,
    int N, int K, const float* __restrict__ bias,
    float* __restrict__ oq, float* __restrict__ ok_, float* __restrict__ ov) {
    extern __shared__ float sm[];
    const int tid = threadIdx.x, lane = tid & 31, w = tid >> 5;
    const int wm = w & 1, wn = w >> 1, g = lane >> 2, qt = lane & 3;
    const int m0 = blockIdx.y * 128, n0 = blockIdx.x * 128;
    const int KT = K / 32;
    const uint32_t smb = sa(sm);

    float acc[4][4][4];
    #pragma unroll
    for (int a = 0; a < 4; a++)
        #pragma unroll
        for (int b = 0; b < 4; b++)
            #pragma unroll
            for (int c = 0; c < 4; c++) acc[a][b][c] = 0.f;

    auto issue = [&](int kt) {
        const int st = kt & 1;
        const uint32_t sA = smb + (uint32_t)st * 9216u * 4u;
        const uint32_t sB = sA + 4608u * 4u;
        const int k0 = kt * 32;
        #pragma unroll
        for (int i = 0; i < 4; i++) {
            int id = tid + i * 256;
            int r = id >> 3, c = (id & 7) * 4;
            cp16(sA + (uint32_t)(r * 36 + c) * 4u, A + (size_t)(m0 + r) * K + k0 + c);
        }
        #pragma unroll
        for (int i = 0; i < 4; i++) {
            int id = tid + i * 256;
            int r = id >> 3, c = (id & 7) * 4;
            cp16(sB + (uint32_t)(r * 36 + c) * 4u, B + (size_t)(n0 + r) * K + k0 + c);
        }
    };

    issue(0); cp_commit();

    const int arow = wm * 64 + (lane & 7) + (lane & 8);
    const int acol = 4 * (lane >> 4);
    const int brow = (lane & 7) + 8 * (lane >> 4);
    const int bcol = 4 * ((lane >> 3) & 1);

    for (int kt = 0; kt < KT; kt++) {
        cp_wait<0>();
        __syncthreads();
        if (kt + 1 < KT) { issue(kt + 1); cp_commit(); }
        const int st = kt & 1;
        const uint32_t sA = smb + (uint32_t)st * 9216u * 4u;
        const uint32_t sB = sA + 4608u * 4u;
        #pragma unroll
        for (int ks = 0; ks < 4; ks++) {
            const int kb = ks * 8;
            uint32_t af[4][4], bf[2][4];
            #pragma unroll
            for (int im = 0; im < 4; im++)
                ldsm4(af[im], sA + (uint32_t)((arow + im * 16) * 36 + kb + acol) * 4u);
            #pragma unroll
            for (int p = 0; p < 2; p++)
                ldsm4(bf[p], sB + (uint32_t)((wn * 32 + p * 16 + brow) * 36 + kb + bcol) * 4u);
            #pragma unroll
            for (int im = 0; im < 4; im++)
                #pragma unroll
                for (int jn = 0; jn < 4; jn++)
                    mma8(acc[im][jn], af[im], bf[jn >> 1][(jn & 1) * 2],
                         bf[jn >> 1][(jn & 1) * 2 + 1]);
        }
        __syncthreads();   // all warps done reading stage st before it is re-filled
    }

    #pragma unroll
    for (int im = 0; im < 4; im++) {
        int mr = m0 + wm * 64 + im * 16 + g;
        #pragma unroll
        for (int jn = 0; jn < 4; jn++) {
            int nc = n0 + wn * 32 + jn * 8 + 2 * qt;
            epi<MODE>(mr,     nc,     acc[im][jn][0], N, bias, out, oq, ok_, ov);
            epi<MODE>(mr,     nc + 1, acc[im][jn][1], N, bias, out, oq, ok_, ov);
            epi<MODE>(mr + 8, nc,     acc[im][jn][2], N, bias, out, oq, ok_, ov);
            epi<MODE>(mr + 8, nc + 1, acc[im][jn][3], N, bias, out, oq, ok_, ov);
        }
    }
}

// -------- flash attention: per CTA one (bh, 128-row q block); 8 warps x 16 rows --------
// q [bh][s][d] (scaled+rounded), k [bh][s][d] (rounded), v [bh][d][s] (rounded)
// smem: Ks[128][132], Vs[128][132], Ps[128][132]
__global__ void __launch_bounds__(256, 1) flash_k(
    const float* __restrict__ q, const float* __restrict__ k, const float* __restrict__ v,
    const float* __restrict__ mask, float* __restrict__ ctx) {
    extern __shared__ float sm[];
    const int tid = threadIdx.x, lane = tid & 31, w = tid >> 5;
    const int g = lane >> 2, qt = lane & 3;
    const int qb = blockIdx.x, bh = blockIdx.y, b = bh >> 5, h = bh & 31;
    const size_t hoff = (size_t)bh * 131072;
    const uint32_t smb = sa(sm);
    const uint32_t sK = smb, sV = smb + 16896u * 4u, sP = smb + 33792u * 4u;

    const int arow = w * 16 + (lane & 7) + (lane & 8);
    const int acol = 4 * (lane >> 4);
    const int brow = (lane & 7) + 8 * (lane >> 4);
    const int bcol = 4 * ((lane >> 3) & 1);

    // stage Q through Ks buffer, pull fragments into registers (live whole kernel)
    #pragma unroll
    for (int i = 0; i < 16; i++) {
        int id = tid + i * 256;
        int r = id >> 5, c = (id & 31) * 4;
        cp16(sK + (uint32_t)(r * 132 + c) * 4u, q + hoff + (size_t)(qb * 128 + r) * 128 + c);
    }
    cp_commit(); cp_wait<0>();
    __syncthreads();
    uint32_t qf[16][4];
    #pragma unroll
    for (int kf = 0; kf < 16; kf++)
        ldsm4(qf[kf], sK + (uint32_t)(arow * 132 + kf * 8 + acol) * 4u);
    __syncthreads();

    float ctxa[16][4];
    #pragma unroll
    for (int i = 0; i < 16; i++) { ctxa[i][0] = ctxa[i][1] = ctxa[i][2] = ctxa[i][3] = 0.f; }
    float m1 = -1e30f, m2 = -1e30f, l1 = 0.f, l2 = 0.f;
    const int rl1 = w * 16 + g, rl2 = rl1 + 8;

    for (int j = 0; j <= qb; j++) {
        #pragma unroll
        for (int i = 0; i < 16; i++) {
            int id = tid + i * 256;
            int r = id >> 5, c = (id & 31) * 4;
            cp16(sK + (uint32_t)(r * 132 + c) * 4u, k + hoff + (size_t)(j * 128 + r) * 128 + c);
        }
        cp_commit();
        #pragma unroll
        for (int i = 0; i < 16; i++) {
            int id = tid + i * 256;
            int r = id >> 5, c = (id & 31) * 4;
            cp16(sV + (uint32_t)(r * 132 + c) * 4u, v + hoff + (size_t)r * 1024 + j * 128 + c);
        }
        cp_commit();
        cp_wait<1>();          // Ks ready; Vs still in flight (overlaps QK^T)
        __syncthreads();

        // S = Q @ K^T  (warp: 16 rows x 128 cols)
        float sacc[16][4];
        #pragma unroll
        for (int i = 0; i < 16; i++) { sacc[i][0] = sacc[i][1] = sacc[i][2] = sacc[i][3] = 0.f; }
        #pragma unroll
        for (int ks = 0; ks < 16; ks++) {
            #pragma unroll
            for (int p = 0; p < 8; p++) {
                uint32_t bf[4];
                ldsm4(bf, sK + (uint32_t)((p * 16 + brow) * 132 + ks * 8 + bcol) * 4u);
                mma8(sacc[2 * p],     qf[ks], bf[0], bf[1]);
                mma8(sacc[2 * p + 1], qf[ks], bf[2], bf[3]);
            }
        }

        // online softmax (row stats warp-local; lanes 4g..4g+3 share rows)
        const bool diag = (j == qb);
        float mx1 = -1e30f, mx2 = -1e30f;
        #pragma unroll
        for (int nf = 0; nf < 16; nf++) {
            int c0 = nf * 8 + 2 * qt, cg = j * 128 + c0;
            float mk0 = __ldg(mask + b * 1024 + cg);
            float mk1 = __ldg(mask + b * 1024 + cg + 1);
            float s0 = sacc[nf][0] + mk0, s1 = sacc[nf][1] + mk1;
            float s2 = sacc[nf][2] + mk0, s3 = sacc[nf][3] + mk1;
            if (diag) {
                if (c0     > rl1) s0 = -1e30f;
                if (c0 + 1 > rl1) s1 = -1e30f;
                if (c0     > rl2) s2 = -1e30f;
                if (c0 + 1 > rl2) s3 = -1e30f;
            }
            sacc[nf][0] = s0; sacc[nf][1] = s1; sacc[nf][2] = s2; sacc[nf][3] = s3;
            mx1 = fmaxf(mx1, fmaxf(s0, s1));
            mx2 = fmaxf(mx2, fmaxf(s2, s3));
        }
        #pragma unroll
        for (int o = 1; o < 4; o <<= 1) {
            mx1 = fmaxf(mx1, __shfl_xor_sync(0xffffffffu, mx1, o));
            mx2 = fmaxf(mx2, __shfl_xor_sync(0xffffffffu, mx2, o));
        }
        float mn1 = fmaxf(m1, mx1), mn2 = fmaxf(m2, mx2);
        float sc1 = __expf(m1 - mn1), sc2 = __expf(m2 - mn2);
        float su1 = 0.f, su2 = 0.f;
        #pragma unroll
        for (int nf = 0; nf < 16; nf++) {
            float p0 = __expf(sacc[nf][0] - mn1), p1 = __expf(sacc[nf][1] - mn1);
            float p2 = __expf(sacc[nf][2] - mn2), p3 = __expf(sacc[nf][3] - mn2);
            su1 += p0 + p1;
            su2 += p2 + p3;
            int c0 = nf * 8 + 2 * qt;
            *(float2*)(sm + 33792 + rl1 * 132 + c0) = make_float2(f2tf(p0), f2tf(p1));
            *(float2*)(sm + 33792 + rl2 * 132 + c0) = make_float2(f2tf(p2), f2tf(p3));
        }
        #pragma unroll
        for (int o = 1; o < 4; o <<= 1) {
            su1 += __shfl_xor_sync(0xffffffffu, su1, o);
            su2 += __shfl_xor_sync(0xffffffffu, su2, o);
        }
        l1 = l1 * sc1 + su1;
        l2 = l2 * sc2 + su2;
        m1 = mn1; m2 = mn2;
        #pragma unroll
        for (int nf = 0; nf < 16; nf++) {
            ctxa[nf][0] *= sc1; ctxa[nf][1] *= sc1;
            ctxa[nf][2] *= sc2; ctxa[nf][3] *= sc2;
        }
        cp_wait<0>();          // Vs ready
        __syncthreads();       // Ps visible to all

        // ctx += P @ V  (k-dim = s; B = Vs[d][s])
        #pragma unroll
        for (int ks = 0; ks < 16; ks++) {
            uint32_t paf[4];
            ldsm4(paf, sP + (uint32_t)(arow * 132 + ks * 8 + acol) * 4u);
            #pragma unroll
            for (int p = 0; p < 8; p++) {
                uint32_t bf[4];
                ldsm4(bf, sV + (uint32_t)((p * 16 + brow) * 132 + ks * 8 + bcol) * 4u);
                mma8(ctxa[2 * p],     paf, bf[0], bf[1]);
                mma8(ctxa[2 * p + 1], paf, bf[2], bf[3]);
            }
        }
        __syncthreads();       // done with Ks/Vs/Ps before next j overwrites
    }

    // epilogue: normalize, round, write [b*s][h*d]
    float il1 = 1.f / l1, il2 = 1.f / l2;
    const int sr1 = qb * 128 + rl1, sr2 = qb * 128 + rl2;
    #pragma unroll
    for (int nf = 0; nf < 16; nf++) {
        int d0 = nf * 8 + 2 * qt;
        size_t o1 = ((size_t)(b * 1024 + sr1)) * 4096 + h * 128 + d0;
        size_t o2 = ((size_t)(b * 1024 + sr2)) * 4096 + h * 128 + d0;
        *(float2*)(ctx + o1) = make_float2(f2tf(ctxa[nf][0] * il1), f2tf(ctxa[nf][1] * il1));
        *(float2*)(ctx + o2) = make_float2(f2tf(ctxa[nf][2] * il2), f2tf(ctxa[nf][3] * il2));
    }
}

// -------- launch --------
extern "C" void kernel_launch(void* const* d_in, const int* in_sizes, int n_in,
                              void* d_out, int out_size) {
    const float* x    = (const float*)d_in[0];
    const float* mask = (const float*)d_in[1];
    const float* nw   = (const float*)d_in[2];
    const float* nb   = (const float*)d_in[3];
    const float* qkvw = (const float*)d_in[4];
    const float* qkvb = (const float*)d_in[5];
    const float* ow   = (const float*)d_in[6];
    float* out = (float*)d_out;

    float *xn, *qv, *kv, *vv, *wbuf, *ctx;
    cudaGetSymbolAddress((void**)&xn,   g_xn);
    cudaGetSymbolAddress((void**)&qv,   g_q);
    cudaGetSymbolAddress((void**)&kv,   g_k);
    cudaGetSymbolAddress((void**)&vv,   g_v);
    cudaGetSymbolAddress((void**)&wbuf, g_w);
    cudaGetSymbolAddress((void**)&ctx,  g_ctx);
    float* wT  = wbuf;               // [12288][4096]
    float* owT = wbuf + 50331648;    // [4096][4096]

    cudaFuncSetAttribute(gemm_k<0>, cudaFuncAttributeMaxDynamicSharedMemorySize, 73728);
    cudaFuncSetAttribute(gemm_k<3>, cudaFuncAttributeMaxDynamicSharedMemorySize, 73728);
    cudaFuncSetAttribute(flash_k,   cudaFuncAttributeMaxDynamicSharedMemorySize, 202752);

    // weight prep: rna-round + transpose to [N][K]
    transpose_round<<<dim3(384, 128), 256>>>(qkvw, wT, 4096, 12288);
    transpose_round<<<dim3(128, 128), 256>>>(ow, owT, 4096, 4096);

    // layernorm (rounded output)
    ln_kernel<<<MTOK, 256>>>(x, nw, nb, xn);

    // QKV GEMM + bias + scatter (q scaled, v transposed, all rounded)
    gemm_k<0><<<dim3(96, 16), 256, 73728>>>(xn, wT, nullptr, 12288, HID, qkvb, qv, kv, vv);

    // fused flash attention -> ctx
    flash_k<<<dim3(8, BHTOT), 256, 202752>>>(qv, kv, vv, mask, ctx);

    // output projection
    gemm_k<3><<<dim3(32, 16), 256, 73728>>>(ctx, owT, out, HID, HID, nullptr,
                                            nullptr, nullptr, nullptr);
}

// round 8
// speedup vs baseline: 2.3337x; 1.0207x over previous
#include <cuda_runtime.h>
#include <cstdint>
#include <math.h>

// Problem constants
#define HID   4096
#define NHEAD 32
#define HDIM  128
#define BATCH 2
#define SEQ   1024
#define MTOK  2048
#define BHTOT 64
#define QSCALE 0.08838834764831845f   // 1/sqrt(128)

// -------- scratch (__device__ globals; no allocation allowed) --------
__device__ float g_xn [MTOK * HID];            // rna-rounded layernorm output
__device__ float g_q  [BHTOT * SEQ * HDIM];    // [bh][s][d], rounded, pre-scaled
__device__ float g_k  [BHTOT * SEQ * HDIM];    // [bh][s][d], rounded
__device__ float g_v  [BHTOT * SEQ * HDIM];    // [bh][d][s], rounded, TRANSPOSED
__device__ float g_w  [67108864];              // qkv_w^T (50331648) + ow^T (16777216)
__device__ float g_ctx[MTOK * HID];            // [b*s][h*d], rounded

// -------- low-level helpers --------
__device__ __forceinline__ float f2tf(float x) {
    uint32_t u;
    asm("cvt.rna.tf32.f32 %0, %1;" : "=r"(u) : "f"(x));
    return __uint_as_float(u);
}
__device__ __forceinline__ uint32_t sa(const void* p) {
    return (uint32_t)__cvta_generic_to_shared(p);
}
__device__ __forceinline__ void cp16(uint32_t s, const void* g) {
    asm volatile("cp.async.cg.shared.global [%0], [%1], 16;\n" :: "r"(s), "l"(g));
}
__device__ __forceinline__ void cp_commit() {
    asm volatile("cp.async.commit_group;\n");
}
template<int N>
__device__ __forceinline__ void cp_wait() {
    asm volatile("cp.async.wait_group %0;\n" :: "n"(N));
}
// ldmatrix x4 on 32-bit data: each 16B "row" = 4 tf32; lane i receives the
// tf32 at (row i>>2, col i&3) per 8x8 matrix -> exactly the tf32 mma frag.
__device__ __forceinline__ void ldsm4(uint32_t r[4], uint32_t a) {
    asm volatile("ldmatrix.sync.aligned.m8n8.x4.shared.b16 {%0,%1,%2,%3}, [%4];"
        : "=r"(r[0]), "=r"(r[1]), "=r"(r[2]), "=r"(r[3]) : "r"(a));
}
__device__ __forceinline__ void mma8(float c[4], const uint32_t a[4],
                                     uint32_t b0, uint32_t b1) {
    asm volatile(
        "mma.sync.aligned.m16n8k8.row.col.f32.tf32.tf32.f32 "
        "{%0,%1,%2,%3}, {%4,%5,%6,%7}, {%8,%9}, {%0,%1,%2,%3};"
        : "+f"(c[0]), "+f"(c[1]), "+f"(c[2]), "+f"(c[3])
        : "r"(a[0]), "r"(a[1]), "r"(a[2]), "r"(a[3]), "r"(b0), "r"(b1));
}

__device__ __forceinline__ float block_sum(float v) {
    __shared__ float sh[8];
    __syncthreads();
    #pragma unroll
    for (int o = 16; o; o >>= 1) v += __shfl_xor_sync(0xffffffffu, v, o);
    if ((threadIdx.x & 31) == 0) sh[threadIdx.x >> 5] = v;
    __syncthreads();
    v = sh[0];
    #pragma unroll
    for (int i = 1; i < 8; i++) v += sh[i];
    return v;
}

// -------- weight prep: transpose [R][C] -> [C][R] with rna rounding --------
__global__ void transpose_round(const float* __restrict__ in, float* __restrict__ out,
                                int R, int C) {
    __shared__ float t[32][33];
    const int tx = threadIdx.x & 31, ty = threadIdx.x >> 5;
    const int c0 = blockIdx.x * 32, r0 = blockIdx.y * 32;
    #pragma unroll
    for (int i = 0; i < 4; i++)
        t[ty + i * 8][tx] = in[(size_t)(r0 + ty + i * 8) * C + c0 + tx];
    __syncthreads();
    #pragma unroll
    for (int i = 0; i < 4; i++)
        out[(size_t)(c0 + ty + i * 8) * R + r0 + tx] = f2tf(t[tx][ty + i * 8]);
}

// -------- layernorm (rna-rounded output) --------
__global__ void ln_kernel(const float* __restrict__ x, const float* __restrict__ w,
                          const float* __restrict__ bb, float* __restrict__ o) {
    size_t base = (size_t)blockIdx.x * HID;
    float4 vx[4];
    float s = 0.f, s2 = 0.f;
    #pragma unroll
    for (int i = 0; i < 4; i++) {
        vx[i] = *(const float4*)(x + base + (size_t)(threadIdx.x + i * 256) * 4);
        s  += vx[i].x + vx[i].y + vx[i].z + vx[i].w;
        s2 += vx[i].x * vx[i].x + vx[i].y * vx[i].y + vx[i].z * vx[i].z + vx[i].w * vx[i].w;
    }
    s  = block_sum(s);
    s2 = block_sum(s2);
    float mu  = s * (1.f / HID);
    float var = s2 * (1.f / HID) - mu * mu;
    float rs  = rsqrtf(var + 1e-5f);
    #pragma unroll
    for (int i = 0; i < 4; i++) {
        int c = (threadIdx.x + i * 256) * 4;
        float4 wv = *(const float4*)(w + c);
        float4 bv = *(const float4*)(bb + c);
        float4 r;
        r.x = f2tf((vx[i].x - mu) * rs * wv.x + bv.x);
        r.y = f2tf((vx[i].y - mu) * rs * wv.y + bv.y);
        r.z = f2tf((vx[i].z - mu) * rs * wv.z + bv.z);
        r.w = f2tf((vx[i].w - mu) * rs * wv.w + bv.w);
        *(float4*)(o + base + c) = r;
    }
}

// -------- GEMM: C[M,N] = A[M,K] @ B[N,K]^T, 128x128x32 --------
// 3-stage cp.async pipeline (wait_group 1 => one tile always in flight),
// single barrier per k-slice, occupancy 2 (108KB smem x2 = 216KB/SM, <=128 regs).
// Grid is (M_blocks, N_blocks): M is the FAST axis -> wave = tall panel, A stays
// L2-resident, each B tile consumed by its 16 M-blocks concurrently.
// MODE 0: QKV epilogue (+bias, scatter q/k/v; q scaled; v transposed; all rounded)
// MODE 3: plain store
template<int MODE>
__device__ __forceinline__ void epi(int m, int n, float val, int N,
                                    const float* __restrict__ bias,
                                    float* __restrict__ out, float* __restrict__ oq,
                                    float* __restrict__ ok_, float* __restrict__ ov) {
    if (MODE == 0) {
        val += bias[n];
        int which = n >> 12, nn = n & 4095;
        int h = nn >> 7, d = nn & 127, b = m >> 10, s = m & 1023;
        int bh = b * NHEAD + h;
        if (which == 0)      oq [((size_t)bh * 1024 + s) * 128 + d] = f2tf(val * QSCALE);
        else if (which == 1) ok_[((size_t)bh * 1024 + s) * 128 + d] = f2tf(val);
        else                 ov [((size_t)bh * 128 + d) * 1024 + s] = f2tf(val);
    } else {
        out[(size_t)m * N + n] = val;
    }
}

template<int MODE>
__global__ void __launch_bounds__(256, 2) gemm_k(
    const float* __restrict__ A, const float* __restrict__ B, float* __restrict__ out,
    int N, int K, const float* __restrict__ bias,
    float* __restrict__ oq, float* __restrict__ ok_, float* __restrict__ ov) {
    extern __shared__ float sm[];
    const int tid = threadIdx.x, lane = tid & 31, w = tid >> 5;
    const int wm = w & 1, wn = w >> 1, g = lane >> 2, qt = lane & 3;
    const int m0 = blockIdx.x * 128, n0 = blockIdx.y * 128;   // M fast axis
    const int KT = K / 32;
    const uint32_t smb = sa(sm);

    float acc[4][4][4];
    #pragma unroll
    for (int a = 0; a < 4; a++)
        #pragma unroll
        for (int b = 0; b < 4; b++)
            #pragma unroll
            for (int c = 0; c < 4; c++) acc[a][b][c] = 0.f;

    auto issue = [&](int kt, int st) {
        const uint32_t sA = smb + (uint32_t)st * 9216u * 4u;
        const uint32_t sB = sA + 4608u * 4u;
        const int k0 = kt * 32;
        #pragma unroll
        for (int i = 0; i < 4; i++) {
            int id = tid + i * 256;
            int r = id >> 3, c = (id & 7) * 4;
            cp16(sA + (uint32_t)(r * 36 + c) * 4u, A + (size_t)(m0 + r) * K + k0 + c);
        }
        #pragma unroll
        for (int i = 0; i < 4; i++) {
            int id = tid + i * 256;
            int r = id >> 3, c = (id & 7) * 4;
            cp16(sB + (uint32_t)(r * 36 + c) * 4u, B + (size_t)(n0 + r) * K + k0 + c);
        }
    };

    issue(0, 0); cp_commit();
    issue(1, 1); cp_commit();

    const int arow = wm * 64 + (lane & 7) + (lane & 8);
    const int acol = 4 * (lane >> 4);
    const int brow = (lane & 7) + 8 * (lane >> 4);
    const int bcol = 4 * ((lane >> 3) & 1);

    int st_r = 0, st_w = 2;
    for (int kt = 0; kt < KT; kt++) {
        cp_wait<1>();
        __syncthreads();               // single barrier per slice (see notes)
        if (kt + 2 < KT) issue(kt + 2, st_w);
        cp_commit();                   // commit every iter: keeps group count exact
        if (++st_w == 3) st_w = 0;
        const uint32_t sA = smb + (uint32_t)st_r * 9216u * 4u;
        const uint32_t sB = sA + 4608u * 4u;
        if (++st_r == 3) st_r = 0;
        #pragma unroll
        for (int ks = 0; ks < 4; ks++) {
            const int kb = ks * 8;
            uint32_t af[4][4], bf[2][4];
            #pragma unroll
            for (int im = 0; im < 4; im++)
                ldsm4(af[im], sA + (uint32_t)((arow + im * 16) * 36 + kb + acol) * 4u);
            #pragma unroll
            for (int p = 0; p < 2; p++)
                ldsm4(bf[p], sB + (uint32_t)((wn * 32 + p * 16 + brow) * 36 + kb + bcol) * 4u);
            #pragma unroll
            for (int im = 0; im < 4; im++)
                #pragma unroll
                for (int jn = 0; jn < 4; jn++)
                    mma8(acc[im][jn], af[im], bf[jn >> 1][(jn & 1) * 2],
                         bf[jn >> 1][(jn & 1) * 2 + 1]);
        }
    }

    #pragma unroll
    for (int im = 0; im < 4; im++) {
        int mr = m0 + wm * 64 + im * 16 + g;
        #pragma unroll
        for (int jn = 0; jn < 4; jn++) {
            int nc = n0 + wn * 32 + jn * 8 + 2 * qt;
            epi<MODE>(mr,     nc,     acc[im][jn][0], N, bias, out, oq, ok_, ov);
            epi<MODE>(mr,     nc + 1, acc[im][jn][1], N, bias, out, oq, ok_, ov);
            epi<MODE>(mr + 8, nc,     acc[im][jn][2], N, bias, out, oq, ok_, ov);
            epi<MODE>(mr + 8, nc + 1, acc[im][jn][3], N, bias, out, oq, ok_, ov);
        }
    }
}

// -------- flash attention: per CTA one (bh, 128-row q block); 8 warps x 16 rows --------
// q [bh][s][d] (scaled+rounded), k [bh][s][d] (rounded), v [bh][d][s] (rounded)
// smem: Ks[128][132], Vs[128][132], Ps[128][132]
__global__ void __launch_bounds__(256, 1) flash_k(
    const float* __restrict__ q, const float* __restrict__ k, const float* __restrict__ v,
    const float* __restrict__ mask, float* __restrict__ ctx) {
    extern __shared__ float sm[];
    const int tid = threadIdx.x, lane = tid & 31, w = tid >> 5;
    const int g = lane >> 2, qt = lane & 3;
    const int qb = blockIdx.x, bh = blockIdx.y, b = bh >> 5, h = bh & 31;
    const size_t hoff = (size_t)bh * 131072;
    const uint32_t smb = sa(sm);
    const uint32_t sK = smb, sV = smb + 16896u * 4u, sP = smb + 33792u * 4u;

    const int arow = w * 16 + (lane & 7) + (lane & 8);
    const int acol = 4 * (lane >> 4);
    const int brow = (lane & 7) + 8 * (lane >> 4);
    const int bcol = 4 * ((lane >> 3) & 1);

    // stage Q through Ks buffer, pull fragments into registers (live whole kernel)
    #pragma unroll
    for (int i = 0; i < 16; i++) {
        int id = tid + i * 256;
        int r = id >> 5, c = (id & 31) * 4;
        cp16(sK + (uint32_t)(r * 132 + c) * 4u, q + hoff + (size_t)(qb * 128 + r) * 128 + c);
    }
    cp_commit(); cp_wait<0>();
    __syncthreads();
    uint32_t qf[16][4];
    #pragma unroll
    for (int kf = 0; kf < 16; kf++)
        ldsm4(qf[kf], sK + (uint32_t)(arow * 132 + kf * 8 + acol) * 4u);
    __syncthreads();

    float ctxa[16][4];
    #pragma unroll
    for (int i = 0; i < 16; i++) { ctxa[i][0] = ctxa[i][1] = ctxa[i][2] = ctxa[i][3] = 0.f; }
    float m1 = -1e30f, m2 = -1e30f, l1 = 0.f, l2 = 0.f;
    const int rl1 = w * 16 + g, rl2 = rl1 + 8;

    for (int j = 0; j <= qb; j++) {
        #pragma unroll
        for (int i = 0; i < 16; i++) {
            int id = tid + i * 256;
            int r = id >> 5, c = (id & 31) * 4;
            cp16(sK + (uint32_t)(r * 132 + c) * 4u, k + hoff + (size_t)(j * 128 + r) * 128 + c);
        }
        cp_commit();
        #pragma unroll
        for (int i = 0; i < 16; i++) {
            int id = tid + i * 256;
            int r = id >> 5, c = (id & 31) * 4;
            cp16(sV + (uint32_t)(r * 132 + c) * 4u, v + hoff + (size_t)r * 1024 + j * 128 + c);
        }
        cp_commit();
        cp_wait<1>();          // Ks ready; Vs still in flight (overlaps QK^T)
        __syncthreads();

        // S = Q @ K^T  (warp: 16 rows x 128 cols)
        float sacc[16][4];
        #pragma unroll
        for (int i = 0; i < 16; i++) { sacc[i][0] = sacc[i][1] = sacc[i][2] = sacc[i][3] = 0.f; }
        #pragma unroll
        for (int ks = 0; ks < 16; ks++) {
            #pragma unroll
            for (int p = 0; p < 8; p++) {
                uint32_t bf[4];
                ldsm4(bf, sK + (uint32_t)((p * 16 + brow) * 132 + ks * 8 + bcol) * 4u);
                mma8(sacc[2 * p],     qf[ks], bf[0], bf[1]);
                mma8(sacc[2 * p + 1], qf[ks], bf[2], bf[3]);
            }
        }

        // online softmax (row stats warp-local; lanes 4g..4g+3 share rows)
        const bool diag = (j == qb);
        float mx1 = -1e30f, mx2 = -1e30f;
        #pragma unroll
        for (int nf = 0; nf < 16; nf++) {
            int c0 = nf * 8 + 2 * qt, cg = j * 128 + c0;
            float mk0 = __ldg(mask + b * 1024 + cg);
            float mk1 = __ldg(mask + b * 1024 + cg + 1);
            float s0 = sacc[nf][0] + mk0, s1 = sacc[nf][1] + mk1;
            float s2 = sacc[nf][2] + mk0, s3 = sacc[nf][3] + mk1;
            if (diag) {
                if (c0     > rl1) s0 = -1e30f;
                if (c0 + 1 > rl1) s1 = -1e30f;
                if (c0     > rl2) s2 = -1e30f;
                if (c0 + 1 > rl2) s3 = -1e30f;
            }
            sacc[nf][0] = s0; sacc[nf][1] = s1; sacc[nf][2] = s2; sacc[nf][3] = s3;
            mx1 = fmaxf(mx1, fmaxf(s0, s1));
            mx2 = fmaxf(mx2, fmaxf(s2, s3));
        }
        #pragma unroll
        for (int o = 1; o < 4; o <<= 1) {
            mx1 = fmaxf(mx1, __shfl_xor_sync(0xffffffffu, mx1, o));
            mx2 = fmaxf(mx2, __shfl_xor_sync(0xffffffffu, mx2, o));
        }
        float mn1 = fmaxf(m1, mx1), mn2 = fmaxf(m2, mx2);
        float sc1 = __expf(m1 - mn1), sc2 = __expf(m2 - mn2);
        float su1 = 0.f, su2 = 0.f;
        #pragma unroll
        for (int nf = 0; nf < 16; nf++) {
            float p0 = __expf(sacc[nf][0] - mn1), p1 = __expf(sacc[nf][1] - mn1);
            float p2 = __expf(sacc[nf][2] - mn2), p3 = __expf(sacc[nf][3] - mn2);
            su1 += p0 + p1;
            su2 += p2 + p3;
            int c0 = nf * 8 + 2 * qt;
            *(float2*)(sm + 33792 + rl1 * 132 + c0) = make_float2(f2tf(p0), f2tf(p1));
            *(float2*)(sm + 33792 + rl2 * 132 + c0) = make_float2(f2tf(p2), f2tf(p3));
        }
        #pragma unroll
        for (int o = 1; o < 4; o <<= 1) {
            su1 += __shfl_xor_sync(0xffffffffu, su1, o);
            su2 += __shfl_xor_sync(0xffffffffu, su2, o);
        }
        l1 = l1 * sc1 + su1;
        l2 = l2 * sc2 + su2;
        m1 = mn1; m2 = mn2;
        #pragma unroll
        for (int nf = 0; nf < 16; nf++) {
            ctxa[nf][0] *= sc1; ctxa[nf][1] *= sc1;
            ctxa[nf][2] *= sc2; ctxa[nf][3] *= sc2;
        }
        cp_wait<0>();          // Vs ready
        __syncthreads();       // Ps visible to all

        // ctx += P @ V  (k-dim = s; B = Vs[d][s])
        #pragma unroll
        for (int ks = 0; ks < 16; ks++) {
            uint32_t paf[4];
            ldsm4(paf, sP + (uint32_t)(arow * 132 + ks * 8 + acol) * 4u);
            #pragma unroll
            for (int p = 0; p < 8; p++) {
                uint32_t bf[4];
                ldsm4(bf, sV + (uint32_t)((p * 16 + brow) * 132 + ks * 8 + bcol) * 4u);
                mma8(ctxa[2 * p],     paf, bf[0], bf[1]);
                mma8(ctxa[2 * p + 1], paf, bf[2], bf[3]);
            }
        }
        __syncthreads();       // done with Ks/Vs/Ps before next j overwrites
    }

    // epilogue: normalize, round, write [b*s][h*d]
    float il1 = 1.f / l1, il2 = 1.f / l2;
    const int sr1 = qb * 128 + rl1, sr2 = qb * 128 + rl2;
    #pragma unroll
    for (int nf = 0; nf < 16; nf++) {
        int d0 = nf * 8 + 2 * qt;
        size_t o1 = ((size_t)(b * 1024 + sr1)) * 4096 + h * 128 + d0;
        size_t o2 = ((size_t)(b * 1024 + sr2)) * 4096 + h * 128 + d0;
        *(float2*)(ctx + o1) = make_float2(f2tf(ctxa[nf][0] * il1), f2tf(ctxa[nf][1] * il1));
        *(float2*)(ctx + o2) = make_float2(f2tf(ctxa[nf][2] * il2), f2tf(ctxa[nf][3] * il2));
    }
}

// -------- launch --------
extern "C" void kernel_launch(void* const* d_in, const int* in_sizes, int n_in,
                              void* d_out, int out_size) {
    const float* x    = (const float*)d_in[0];
    const float* mask = (const float*)d_in[1];
    const float* nw   = (const float*)d_in[2];
    const float* nb   = (const float*)d_in[3];
    const float* qkvw = (const float*)d_in[4];
    const float* qkvb = (const float*)d_in[5];
    const float* ow   = (const float*)d_in[6];
    float* out = (float*)d_out;

    float *xn, *qv, *kv, *vv, *wbuf, *ctx;
    cudaGetSymbolAddress((void**)&xn,   g_xn);
    cudaGetSymbolAddress((void**)&qv,   g_q);
    cudaGetSymbolAddress((void**)&kv,   g_k);
    cudaGetSymbolAddress((void**)&vv,   g_v);
    cudaGetSymbolAddress((void**)&wbuf, g_w);
    cudaGetSymbolAddress((void**)&ctx,  g_ctx);
    float* wT  = wbuf;               // [12288][4096]
    float* owT = wbuf + 50331648;    // [4096][4096]

    cudaFuncSetAttribute(gemm_k<0>, cudaFuncAttributeMaxDynamicSharedMemorySize, 110592);
    cudaFuncSetAttribute(gemm_k<3>, cudaFuncAttributeMaxDynamicSharedMemorySize, 110592);
    cudaFuncSetAttribute(flash_k,   cudaFuncAttributeMaxDynamicSharedMemorySize, 202752);

    // weight prep: rna-round + transpose to [N][K]
    transpose_round<<<dim3(384, 128), 256>>>(qkvw, wT, 4096, 12288);
    transpose_round<<<dim3(128, 128), 256>>>(ow, owT, 4096, 4096);

    // layernorm (rounded output)
    ln_kernel<<<MTOK, 256>>>(x, nw, nb, xn);

    // QKV GEMM + bias + scatter (q scaled, v transposed, all rounded)
    // grid: (M_blocks=16 fast, N_blocks=96)
    gemm_k<0><<<dim3(16, 96), 256, 110592>>>(xn, wT, nullptr, 12288, HID, qkvb, qv, kv, vv);

    // fused flash attention -> ctx
    flash_k<<<dim3(8, BHTOT), 256, 202752>>>(qv, kv, vv, mask, ctx);

    // output projection, grid (16, 32)
    gemm_k<3><<<dim3(16, 32), 256, 110592>>>(ctx, owT, out, HID, HID, nullptr,
                                             nullptr, nullptr, nullptr);
}